// round 1
// baseline (speedup 1.0000x reference)
#include <cuda_runtime.h>

// Problem constants (fixed by the reference).
#define SEQ   1024
#define BATCH 512
#define NC    48

// logZ scratch (device global: no allocations allowed).
__device__ float g_logZ[BATCH];

// ---------------------------------------------------------------------------
// Kernel A: forward algorithm (logZ) — one warp per batch element.
//
// Representation: alpha_t[j] = Mlog + log(expA[j]), with expA renormalized
// every step so that expA[class 0] == 1 (divide by u_ref = u[0]).
// expT = exp(transitions) lives in registers: lane owns columns (lane, lane+32).
// expA is exchanged lane->all via shfl (also serves as the warp sync).
// scores rows are prefetched 2 steps ahead (register double buffer).
// ---------------------------------------------------------------------------
__global__ __launch_bounds__(32) void crf_logZ_kernel(
    const float* __restrict__ scores,
    const int*   __restrict__ lengths,
    const float* __restrict__ trans)
{
    const int b    = blockIdx.x;
    const int lane = threadIdx.x;
    const int c0   = lane;         // always < 48
    const int c1   = lane + 32;    // valid only for lane < 16
    const bool v1  = (c1 < NC);

    // Pre-exponentiate transition columns into registers.
    float eT0[NC], eT1[NC];
#pragma unroll
    for (int i = 0; i < NC; ++i) {
        eT0[i] = __expf(trans[i * NC + c0]);
        eT1[i] = v1 ? __expf(trans[i * NC + c1]) : 0.0f;
    }

    const int L = lengths[b];

    // t = 0 init: alpha0 = scores[0][b][:]  ->  expA = exp(alpha0), M = 0.
    float a0 = __expf(scores[(size_t)b * NC + c0]);
    float a1 = v1 ? __expf(scores[(size_t)b * NC + c1]) : 0.0f;
    float Mlog = 0.0f;

    // Prefetch scores rows for t = 1 and t = 2 (clamped; always in-bounds).
    float p0[2], p1[2];
#pragma unroll
    for (int k = 0; k < 2; ++k) {
        int tt = 1 + k;
        if (tt > SEQ - 1) tt = SEQ - 1;
        size_t base = ((size_t)tt * BATCH + b) * NC;
        p0[k] = scores[base + c0];
        p1[k] = v1 ? scores[base + c1] : 0.0f;
    }

    for (int t = 1; t < L; ++t) {
        const int slot = (t - 1) & 1;
        const float s0 = p0[slot];
        const float s1 = p1[slot];

        // Prefetch t+2 into the slot we just consumed (clamped to stay in-bounds).
        int tn = t + 2;
        if (tn > SEQ - 1) tn = SEQ - 1;
        {
            size_t base = ((size_t)tn * BATCH + b) * NC;
            p0[slot] = scores[base + c0];
            p1[slot] = v1 ? scores[base + c1] : 0.0f;
        }

        // Off-critical-chain: per-class emission factors.
        const float w0 = __expf(s0);
        const float w1 = __expf(s1);

        // dot_j = sum_i expA[i] * expT[i][j], expA broadcast via shfl.
        float d00 = 0.f, d01 = 0.f, d02 = 0.f, d03 = 0.f;
        float d10 = 0.f, d11 = 0.f, d12 = 0.f, d13 = 0.f;
#pragma unroll
        for (int i = 0; i < 32; i += 4) {
            float e0 = __shfl_sync(0xffffffffu, a0, i);
            float e1 = __shfl_sync(0xffffffffu, a0, i + 1);
            float e2 = __shfl_sync(0xffffffffu, a0, i + 2);
            float e3 = __shfl_sync(0xffffffffu, a0, i + 3);
            d00 = fmaf(e0, eT0[i],     d00);  d10 = fmaf(e0, eT1[i],     d10);
            d01 = fmaf(e1, eT0[i + 1], d01);  d11 = fmaf(e1, eT1[i + 1], d11);
            d02 = fmaf(e2, eT0[i + 2], d02);  d12 = fmaf(e2, eT1[i + 2], d12);
            d03 = fmaf(e3, eT0[i + 3], d03);  d13 = fmaf(e3, eT1[i + 3], d13);
        }
#pragma unroll
        for (int i = 0; i < 16; i += 4) {
            float e0 = __shfl_sync(0xffffffffu, a1, i);
            float e1 = __shfl_sync(0xffffffffu, a1, i + 1);
            float e2 = __shfl_sync(0xffffffffu, a1, i + 2);
            float e3 = __shfl_sync(0xffffffffu, a1, i + 3);
            d00 = fmaf(e0, eT0[32 + i],     d00);  d10 = fmaf(e0, eT1[32 + i],     d10);
            d01 = fmaf(e1, eT0[32 + i + 1], d01);  d11 = fmaf(e1, eT1[32 + i + 1], d11);
            d02 = fmaf(e2, eT0[32 + i + 2], d02);  d12 = fmaf(e2, eT1[32 + i + 2], d12);
            d03 = fmaf(e3, eT0[32 + i + 3], d03);  d13 = fmaf(e3, eT1[32 + i + 3], d13);
        }
        const float dot0 = (d00 + d01) + (d02 + d03);
        const float dot1 = (d10 + d11) + (d12 + d13);

        const float u0 = dot0 * w0;
        const float u1 = dot1 * w1;

        // Renormalize by u[class 0]: expA'[0] == 1 exactly -> bounded forever.
        const float uref = __shfl_sync(0xffffffffu, u0, 0);
        Mlog += __logf(uref);
        float inv;
        asm("rcp.approx.f32 %0, %1;" : "=f"(inv) : "f"(uref));
        a0 = u0 * inv;
        a1 = v1 ? (u1 * inv) : 0.0f;
    }

    // logZ = Mlog + log(sum_j expA[j])
    float ssum = a0 + a1;
#pragma unroll
    for (int o = 16; o > 0; o >>= 1)
        ssum += __shfl_xor_sync(0xffffffffu, ssum, o);
    if (lane == 0)
        g_logZ[b] = Mlog + __logf(ssum);
}

// ---------------------------------------------------------------------------
// Kernel B: target-path score X (parallel over t), then write both outputs.
// out[b] = X[b];  out[BATCH + b] = X[b] - logZ[b].
// ---------------------------------------------------------------------------
__global__ __launch_bounds__(256) void crf_X_kernel(
    const float* __restrict__ scores,
    const int*   __restrict__ target,
    const int*   __restrict__ lengths,
    const float* __restrict__ trans,
    float*       __restrict__ out)
{
    const int b   = blockIdx.x;
    const int tid = threadIdx.x;
    const int L   = lengths[b];

    float part = 0.0f;
    for (int t = tid; t < L; t += 256) {
        const int tgt = target[t * BATCH + b];
        float v = scores[((size_t)t * BATCH + b) * NC + tgt];
        if (t > 0) {
            const int tp = target[(t - 1) * BATCH + b];
            v += trans[tp * NC + tgt];
        }
        part += v;
    }

    // Block reduction: warp shuffles + tiny shared bounce.
    __shared__ float sh[8];
#pragma unroll
    for (int o = 16; o > 0; o >>= 1)
        part += __shfl_xor_sync(0xffffffffu, part, o);
    if ((tid & 31) == 0) sh[tid >> 5] = part;
    __syncthreads();
    if (tid < 8) {
        float v = sh[tid];
#pragma unroll
        for (int o = 4; o > 0; o >>= 1)
            v += __shfl_xor_sync(0x000000ffu, v, o);
        if (tid == 0) {
            out[b]         = v;
            out[BATCH + b] = v - g_logZ[b];
        }
    }
}

// ---------------------------------------------------------------------------
extern "C" void kernel_launch(void* const* d_in, const int* in_sizes, int n_in,
                              void* d_out, int out_size)
{
    const float* scores  = (const float*)d_in[0];  // (1024, 512, 48) f32
    const int*   target  = (const int*)  d_in[1];  // (1024, 512) i32
    const int*   lengths = (const int*)  d_in[2];  // (512,) i32
    const float* trans   = (const float*)d_in[3];  // (48, 48) f32
    float* out = (float*)d_out;                    // (2, 512) f32

    crf_logZ_kernel<<<BATCH, 32>>>(scores, lengths, trans);
    crf_X_kernel<<<BATCH, 256>>>(scores, target, lengths, trans, out);
}

// round 2
// speedup vs baseline: 1.3562x; 1.3562x over previous
#include <cuda_runtime.h>

#define SEQ   1024
#define BATCH 512
#define NC    48
#define FULL  0xffffffffu

// ---- packed f32x2 helpers (sm_103a) ------------------------------------
static __device__ __forceinline__ unsigned long long pk2(float lo, float hi) {
    unsigned long long r;
    asm("mov.b64 %0, {%1,%2};" : "=l"(r) : "f"(lo), "f"(hi));
    return r;
}
static __device__ __forceinline__ unsigned long long fma2(
    unsigned long long a, unsigned long long b, unsigned long long c) {
    unsigned long long d;
    asm("fma.rn.f32x2 %0, %1, %2, %3;" : "=l"(d) : "l"(a), "l"(b), "l"(c));
    return d;
}
static __device__ __forceinline__ unsigned long long add2(
    unsigned long long a, unsigned long long b) {
    unsigned long long d;
    asm("add.rn.f32x2 %0, %1, %2;" : "=l"(d) : "l"(a), "l"(b));
    return d;
}
static __device__ __forceinline__ float hadd2(unsigned long long v) {
    float lo, hi;
    asm("mov.b64 {%0,%1}, %2;" : "=f"(lo), "=f"(hi) : "l"(v));
    return lo + hi;
}
static __device__ __forceinline__ void lds16(
    unsigned long long& x, unsigned long long& y, unsigned int addr) {
    asm volatile("ld.shared.v2.u64 {%0,%1}, [%2];" : "=l"(x), "=l"(y) : "r"(addr));
}
static __device__ __forceinline__ float frcp(float x) {
    float r; asm("rcp.approx.f32 %0, %1;" : "=f"(r) : "f"(x)); return r;
}

// ---------------------------------------------------------------------------
// Fused kernel. Block = 256 threads, 4 batches per block:
//   warps 0-3: forward algorithm (logZ) for batch 4*blk+wid  (SMSPs 0-3)
//   warps 4-7: target-path score X for batch 4*blk+(wid-4), handed to the
//              matching logZ warp via shared flag (same block -> no deadlock).
//
// logZ math: exp-domain recurrence u_t = diag(w_t) * E^T * u_{t-1},
// E = exp(transitions) held in registers as row-paired f32x2.
// One-step-delayed renormalization: a_t = v_t / a_{t-1}[0], with
// Mlog += log(a_{t-1}[0]) compensating exactly (rcp/log off critical chain).
// alpha exchange via shared ping-pong buffers (1 syncwarp/step).
// ---------------------------------------------------------------------------
__global__ __launch_bounds__(256, 1) void crf_fused_kernel(
    const float* __restrict__ scores,
    const int*   __restrict__ target,
    const int*   __restrict__ lengths,
    const float* __restrict__ trans,
    float*       __restrict__ out)
{
    __shared__ float sh_a[4][2][64];   // [warp][pingpong][48 used + pad]
    __shared__ float sh_X[4];
    __shared__ int   sh_flag[4];

    const int wid  = threadIdx.x >> 5;
    const int lane = threadIdx.x & 31;

    if (wid < 4 && lane == 0) sh_flag[wid] = 0;
    __syncthreads();

    if (wid >= 4) {
        // ---------------- X role (overlapped with logZ loop) ----------------
        const int w = wid - 4;
        const int b = blockIdx.x * 4 + w;
        const int L = lengths[b];
        float part = 0.0f;
        for (int t = lane; t < L; t += 32) {
            const int tgt = target[t * BATCH + b];
            float v = scores[((size_t)t * BATCH + b) * NC + tgt];
            if (t > 0) v += trans[target[(t - 1) * BATCH + b] * NC + tgt];
            part += v;
        }
#pragma unroll
        for (int o = 16; o > 0; o >>= 1)
            part += __shfl_xor_sync(FULL, part, o);
        if (lane == 0) {
            sh_X[w] = part;
            __threadfence_block();
            atomicExch(&sh_flag[w], 1);
        }
        return;
    }

    // ------------------------- logZ role -----------------------------------
    const int  b  = blockIdx.x * 4 + wid;
    const int  c0 = lane;
    const bool v1 = (lane < 16);
    const int  c1 = v1 ? (lane + 32) : lane;   // safe dup index; zeroed below

    // exp(transitions) as row-paired f32x2, one column pair per lane.
    unsigned long long eTp0[24], eTp1[24];
#pragma unroll
    for (int k = 0; k < 24; ++k) {
        float x0 = __expf(trans[(2 * k)     * NC + c0]);
        float y0 = __expf(trans[(2 * k + 1) * NC + c0]);
        eTp0[k] = pk2(x0, y0);
        float x1 = v1 ? __expf(trans[(2 * k)     * NC + c1]) : 0.0f;
        float y1 = v1 ? __expf(trans[(2 * k + 1) * NC + c1]) : 0.0f;
        eTp1[k] = pk2(x1, y1);
    }

    const int L = lengths[b];
    const float* sp0 = scores + (size_t)b * NC + c0;
    const float* sp1 = scores + (size_t)b * NC + c1;

    float a0   = __expf(sp0[0]);
    float a1   = v1 ? __expf(sp1[0]) : 0.0f;
    float Mlog = 0.0f;

    // 2-deep register prefetch of score rows (clamped, always in-bounds).
    float p0[2], p1[2];
#pragma unroll
    for (int k = 0; k < 2; ++k) {
        int tt = 1 + k; if (tt > SEQ - 1) tt = SEQ - 1;
        p0[k] = sp0[(size_t)tt * (BATCH * NC)];
        p1[k] = v1 ? sp1[(size_t)tt * (BATCH * NC)] : 0.0f;
    }

    unsigned int shbase[2];
    shbase[0] = (unsigned int)__cvta_generic_to_shared(&sh_a[wid][0][0]);
    shbase[1] = (unsigned int)__cvta_generic_to_shared(&sh_a[wid][1][0]);

    for (int t = 1; t < L; ++t) {
        const int slot = (t - 1) & 1;

        // Delayed-norm reference: previous alpha's class-0 value (known now).
        const float r   = __shfl_sync(FULL, a0, 0);
        const float inv = frcp(r);
        Mlog += __logf(r);

        const float s0 = p0[slot];
        const float s1 = p1[slot];
        {   // prefetch t+2 (clamped)
            int tn = t + 2; if (tn > SEQ - 1) tn = SEQ - 1;
            p0[slot] = sp0[(size_t)tn * (BATCH * NC)];
            p1[slot] = v1 ? sp1[(size_t)tn * (BATCH * NC)] : 0.0f;
        }
        const float m0 = __expf(s0) * inv;
        const float m1 = __expf(s1) * inv;

        // exchange alpha through shared (ping-pong -> single syncwarp)
        {
            float* shp = &sh_a[wid][slot][0];
            shp[lane]      = a0;
            shp[32 + lane] = a1;
        }
        __syncwarp();

        const unsigned int sb = shbase[slot];
        unsigned long long acc0a = 0ull, acc0b = 0ull;
        unsigned long long acc1a = 0ull, acc1b = 0ull;
#pragma unroll
        for (int k = 0; k < 12; ++k) {
            unsigned long long e01, e23;
            lds16(e01, e23, sb + 16u * k);
            acc0a = fma2(e01, eTp0[2 * k],     acc0a);
            acc0b = fma2(e23, eTp0[2 * k + 1], acc0b);
            acc1a = fma2(e01, eTp1[2 * k],     acc1a);
            acc1b = fma2(e23, eTp1[2 * k + 1], acc1b);
        }
        const float dot0 = hadd2(add2(acc0a, acc0b));
        const float dot1 = hadd2(add2(acc1a, acc1b));

        a0 = dot0 * m0;
        a1 = dot1 * m1;
    }

    // logZ = Mlog + log(sum_j a[j])
    float ssum = a0 + a1;
#pragma unroll
    for (int o = 16; o > 0; o >>= 1)
        ssum += __shfl_xor_sync(FULL, ssum, o);

    if (lane == 0) {
        const float logZ = Mlog + __logf(ssum);
        // X warp of the same block finishes in ~13us << our loop: no real wait.
        while (atomicAdd(&sh_flag[wid], 0) == 0) { }
        __threadfence_block();
        const float X = sh_X[wid];
        out[b]         = X;
        out[BATCH + b] = X - logZ;
    }
}

// ---------------------------------------------------------------------------
extern "C" void kernel_launch(void* const* d_in, const int* in_sizes, int n_in,
                              void* d_out, int out_size)
{
    const float* scores  = (const float*)d_in[0];  // (1024, 512, 48) f32
    const int*   target  = (const int*)  d_in[1];  // (1024, 512) i32
    const int*   lengths = (const int*)  d_in[2];  // (512,) i32
    const float* trans   = (const float*)d_in[3];  // (48, 48) f32
    float* out = (float*)d_out;                    // (2, 512) f32

    crf_fused_kernel<<<BATCH / 4, 256>>>(scores, target, lengths, trans, out);
}